// round 15
// baseline (speedup 1.0000x reference)
#include <cuda_runtime.h>
#include <cuda_fp16.h>
#include <cstdint>

// ---------------- problem constants ----------------
#define NB   32
#define IC   64
#define OCH  128
#define HH   128
#define WW   128
#define OH   126
#define OW   126

// smem: two x buffers + two weight PAIR buffers (2 taps each), rows stride XSTR
#define XSTR     72
#define SX_ROWS  130
#define SX_BYTES (SX_ROWS * XSTR * 2)            // 18720
#define TAPB     (OCH * XSTR * 2)                // 18432 per tap
#define PAIRB    (2 * TAPB)                      // 36864
#define XB0      0
#define XB1      SX_BYTES
#define PB0      (2 * SX_BYTES)
#define PB1      (2 * SX_BYTES + PAIRB)
#define SMEM_BYTES (2 * SX_BYTES + 2 * PAIRB)    // 111168

// pre-converted fp16 weights: g_wh[kk][oc][ic/2] as half2 (row = oc, 64 halves)
__device__ __half2 g_wh[9 * OCH * (IC / 2)];
// pre-transposed fp16 x: g_xh[n][h][w][ic/2]  (ic contiguous)
__device__ __half2 g_xh[(size_t)NB * HH * WW * (IC / 2)];

// merged prologue: x transpose+convert (packed F2FP), weight convert in 9 blocks
__global__ void prep_kernel(const float* __restrict__ x,
                            const float* __restrict__ wg) {
    __shared__ __half s[128 * 66];
    const int h = blockIdx.x, n = blockIdx.y, tid = threadIdx.x;
    const float* src = x + ((size_t)n * IC * HH + h) * WW;
    // phase 1: load ic-pairs, pack to half2, store pair at s[w*66 + 2*icp]
    #pragma unroll
    for (int i = 0; i < 16; i++) {
        int idx = tid + i * 256;          // 0..4095
        int icp = idx >> 7;               // ic pair 0..31
        int w   = idx & 127;
        float v0 = src[(size_t)(2 * icp)     * (HH * WW) + w];
        float v1 = src[(size_t)(2 * icp + 1) * (HH * WW) + w];
        *(__half2*)&s[w * 66 + 2 * icp] = __floats2half2_rn(v0, v1);
    }
    __syncthreads();
    __half2* dst = g_xh + ((size_t)(n * HH + h)) * (WW * 32);
    #pragma unroll
    for (int i = 0; i < 16; i++) {
        int idx = tid + i * 256;
        int w = idx >> 5, icp = idx & 31;
        dst[w * 32 + icp] = *(__half2*)&s[w * 66 + 2 * icp];
    }
    // weight convert: blocks (h<9, n==0), tap kk = h
    if (n == 0 && h < 9) {
        const int kk = h;
        #pragma unroll
        for (int i = 0; i < 16; i++) {
            int idx = tid + i * 256;            // 0..4095 over oc*32+icp
            int oc  = idx >> 5;
            int ic  = (idx & 31) * 2;
            g_wh[kk * (OCH * 32) + idx] =
                __floats2half2_rn(wg[(oc * IC + ic) * 9 + kk],
                                  wg[(oc * IC + ic + 1) * 9 + kk]);
        }
    }
}

__device__ __forceinline__ uint32_t smem_u32(const void* p) {
    uint32_t a;
    asm("{ .reg .u64 t; cvta.to.shared.u64 t, %1; cvt.u32.u64 %0, t; }"
        : "=r"(a) : "l"(p));
    return a;
}
__device__ __forceinline__ void cp16(uint32_t dst, const void* src) {
    asm volatile("cp.async.cg.shared.global [%0], [%1], 16;"
                 :: "r"(dst), "l"(src));
}
__device__ __forceinline__ void ldsm_x4(uint32_t& r0, uint32_t& r1,
                                        uint32_t& r2, uint32_t& r3,
                                        uint32_t addr) {
    asm volatile("ldmatrix.sync.aligned.m8n8.x4.shared.b16 {%0,%1,%2,%3}, [%4];"
                 : "=r"(r0), "=r"(r1), "=r"(r2), "=r"(r3) : "r"(addr));
}
__device__ __forceinline__ void hmma16816(float* c, const uint32_t* a,
                                          uint32_t b0, uint32_t b1) {
    asm volatile(
        "mma.sync.aligned.m16n8k16.row.col.f32.f16.f16.f32 "
        "{%0,%1,%2,%3}, {%4,%5,%6,%7}, {%8,%9}, {%0,%1,%2,%3};"
        : "+f"(c[0]), "+f"(c[1]), "+f"(c[2]), "+f"(c[3])
        : "r"(a[0]), "r"(a[1]), "r"(a[2]), "r"(a[3]), "r"(b0), "r"(b1));
}
__device__ __forceinline__ float frcp(float v) {
    float r;
    asm("rcp.approx.f32 %0, %1;" : "=f"(r) : "f"(v));
    return r;
}

__global__ void __launch_bounds__(256, 2)
conv_hmma_kernel(const float* __restrict__ bias,
                 float* __restrict__ out)
{
    extern __shared__ char smem[];
    const uint32_t sbase = smem_u32(smem);

    const int tid  = threadIdx.x;
    const int lane = tid & 31;
    const int warp = tid >> 5;
    const int g    = lane >> 2;      // group id 0..7
    const int t    = lane & 3;       // thread in group

    const int warp_m = warp & 1;     // 2 warps over M=128 (64 each)
    const int warp_n = warp >> 1;    // 4 warps over N=128 (32 each)

    const int oh0 = blockIdx.x * 2;  // this CTA: output rows oh0, oh0+1
    const int n   = blockIdx.y;

    float c[4][4][4];                // [m-tile][n-tile][reg]
    #pragma unroll
    for (int i = 0; i < 4; i++)
        #pragma unroll
        for (int j = 0; j < 4; j++)
            #pragma unroll
            for (int r = 0; r < 4; r++)
                c[i][j][r] = 0.f;

    // zero halo rows w=128,129 of BOTH x buffers (64 halves = 32 u32 per row)
    if (tid < 128) {
        int bsel = tid >> 6;
        int r    = (tid >> 5) & 1;
        int cc   = tid & 31;
        *(uint32_t*)(smem + (bsel ? XB1 : XB0) +
                     (128 + r) * (XSTR * 2) + cc * 4) = 0;
    }

    const uint32_t xoff[2] = {XB0, XB1};
    const uint32_t poff[2] = {PB0, PB1};
    auto stage_x = [&](uint32_t off, int ih) {
        const __half* xr = (const __half*)g_xh +
                           ((size_t)(n * HH + ih)) * (WW * IC);
        #pragma unroll
        for (int i = 0; i < 4; i++) {
            int idx = tid + i * 256;
            int w = idx >> 3, cc = idx & 7;
            cp16(sbase + off + (uint32_t)((w * XSTR + cc * 8) * 2),
                 xr + w * IC + cc * 8);
        }
    };
    // stage 'cnt' taps starting at tap kk into pair buffer 'off'
    auto stage_taps = [&](uint32_t off, int kk, int cnt) {
        const __half* wr = (const __half*)g_wh + (size_t)kk * (OCH * IC);
        for (int q = 0; q < cnt; q++) {
            #pragma unroll
            for (int i = 0; i < 4; i++) {
                int idx = tid + i * 256;
                int oc = idx >> 3, cc = idx & 7;
                cp16(sbase + off + (uint32_t)(q * TAPB +
                         (oc * XSTR + cc * 8) * 2),
                     wr + (q * OCH + oc) * IC + cc * 8);
            }
        }
    };

    // epilogue for one output row, from current acc
    auto epilogue = [&](int oh) {
        #pragma unroll
        for (int j = 0; j < 4; j++) {
            const int oc0 = warp_n * 32 + j * 8 + 2 * t;
            const float b0 = bias[oc0]     - 0.7f;
            const float b1 = bias[oc0 + 1] - 0.7f;
            #pragma unroll
            for (int i = 0; i < 4; i++) {
                #pragma unroll
                for (int pp = 0; pp < 4; pp += 2) {
                    const int m = warp_m * 64 + i * 16 + g + ((pp & 2) ? 8 : 0);
                    if (m >= OW) continue;
                    float v0 = c[i][j][pp]     + b0;
                    float v1 = c[i][j][pp + 1] + b1;
                    float e0 = __expf(fminf(v0, 15.f));
                    float e1 = __expf(fminf(v1, 15.f));
                    float n0 = e0 * (e0 + 2.f);
                    float n1 = e1 * (e1 + 2.f);
                    float d0 = n0 + 2.f, d1 = n1 + 2.f;
                    float rr = frcp(d0 * d1);
                    float m0 = v0 * n0 * (rr * d1);
                    float m1 = v1 * n1 * (rr * d0);
                    float* ob = out +
                        ((size_t)(n * OCH + oc0) * OH + oh) * OW + m;
                    ob[0]                 = m0;
                    ob[(size_t)(OH * OW)] = m1;
                }
            }
        }
    };

    // ldmatrix per-lane invariant offsets (bytes)
    const int l7 = lane & 7;
    const uint32_t a_lane =
        (uint32_t)(((l7 + ((lane >> 3) & 1) * 8) * XSTR + ((lane >> 4) & 1) * 8) * 2);
    const uint32_t b_lane =
        (uint32_t)(((l7 + ((lane >> 4) & 1) * 8) * XSTR + ((lane >> 3) & 1) * 8) * 2);

    // ---- prologue (critical wait minimized): x row oh0 + taps{0,1} only
    stage_x(XB0, oh0);
    stage_taps(PB0, 0, 2);
    asm volatile("cp.async.commit_group;" ::: "memory");

    // ---- 10 regions = 2 output rows x 5 regions; ONE barrier per region.
    // Region R: ohi=R/5, rg=R%5, taps {2rg, 2rg+1} (last region of each row: 1).
    // x buffers: xbuf(kh, ohi) = (kh + ohi) & 1; restage XB0@R2 (row oh0+2),
    // XB1@R7 (row oh0+3). Pair buffer = R&1, staged one region ahead.
    #pragma unroll
    for (int R = 0; R < 10; R++) {
        const int ohi = R / 5, rg = R % 5;

        asm volatile("cp.async.wait_group 0;" ::: "memory");
        __syncthreads();

        // stage region R+1 (WAR-safe: its pair buffer last read in region R-1;
        // x buffers last read per the map above, all before this barrier)
        if (R < 9) {
            const int rg1 = (R + 1) % 5;
            if (R == 0) stage_x(XB1, oh0 + 1);
            if (R == 2) stage_x(XB0, oh0 + 2);
            if (R == 7) stage_x(XB1, oh0 + 3);
            stage_taps(poff[(R + 1) & 1], 2 * rg1, (rg1 == 4) ? 1 : 2);
        }
        asm volatile("cp.async.commit_group;" ::: "memory");

        const int ntap = (rg == 4) ? 1 : 2;
        #pragma unroll
        for (int q = 0; q < 2; q++) {
            if (q >= ntap) break;
            const int kk = 2 * rg + q;
            const int kh = kk / 3, kw = kk % 3;
            const uint32_t aBase = sbase + xoff[(kh + ohi) & 1] + a_lane +
                                   (uint32_t)((warp_m * 64 + kw) * XSTR * 2);
            const uint32_t bBase = sbase + poff[R & 1] + b_lane +
                                   (uint32_t)(q * TAPB + warp_n * 32 * XSTR * 2);

            #pragma unroll
            for (int ks = 0; ks < 4; ks++) {
                uint32_t a[4][4];
                #pragma unroll
                for (int i = 0; i < 4; i++)
                    ldsm_x4(a[i][0], a[i][1], a[i][2], a[i][3],
                            aBase + (uint32_t)((i * 16 * XSTR + ks * 16) * 2));

                #pragma unroll
                for (int jp = 0; jp < 2; jp++) {
                    uint32_t b0, b1, b2, b3;
                    ldsm_x4(b0, b1, b2, b3,
                            bBase + (uint32_t)((jp * 16 * XSTR + ks * 16) * 2));
                    #pragma unroll
                    for (int i = 0; i < 4; i++) {
                        hmma16816(c[i][jp * 2],     a[i], b0, b1);
                        hmma16816(c[i][jp * 2 + 1], a[i], b2, b3);
                    }
                }
            }
        }

        if (rg == 4) {
            // row ohi done: write it out (overlaps staging committed above),
            // then clear accumulators for the next row.
            epilogue(oh0 + ohi);
            if (ohi == 0) {
                #pragma unroll
                for (int i = 0; i < 4; i++)
                    #pragma unroll
                    for (int j = 0; j < 4; j++)
                        #pragma unroll
                        for (int r = 0; r < 4; r++)
                            c[i][j][r] = 0.f;
            }
        }
    }
}

extern "C" void kernel_launch(void* const* d_in, const int* in_sizes, int n_in,
                              void* d_out, int out_size) {
    const float* x  = (const float*)d_in[0];
    const float* w  = (const float*)d_in[1];
    const float* b  = (const float*)d_in[2];
    float* out      = (float*)d_out;

    {
        dim3 tg(HH, NB);
        prep_kernel<<<tg, 256>>>(x, w);
    }

    cudaFuncSetAttribute(conv_hmma_kernel,
                         cudaFuncAttributeMaxDynamicSharedMemorySize, SMEM_BYTES);
    dim3 grid(OH / 2, NB);   // 63 x 32 CTAs, two output rows each
    conv_hmma_kernel<<<grid, 256, SMEM_BYTES>>>(b, out);
}

// round 16
// speedup vs baseline: 1.0298x; 1.0298x over previous
#include <cuda_runtime.h>
#include <cuda_fp16.h>
#include <cstdint>

// ---------------- problem constants ----------------
#define NB   32
#define IC   64
#define OCH  128
#define HH   128
#define WW   128
#define OH   126
#define OW   126
#define OHP  (OH / 2)          // 63 oh-pairs per image
#define TILES (OHP * NB)       // 2016

// smem: 4-slot x ring (padded 144B rows) + 9 resident swizzled weight taps
#define XSTR     72                              // halves; 144B row
#define SX_BYTES (130 * 144)                     // 18720
#define XRING    (4 * SX_BYTES)                  // 74880
#define WOFF     XRING
#define WTAP     16384                           // 128 oc x 128B swizzled
#define SMEM_BYTES (XRING + 9 * WTAP)            // 222336 <= 227KB

// pre-converted fp16 weights: g_wh[kk][oc][ic/2] as half2
__device__ __half2 g_wh[9 * OCH * (IC / 2)];
// pre-transposed fp16 x: g_xh[n][h][w][ic/2]  (ic contiguous)
__device__ __half2 g_xh[(size_t)NB * HH * WW * (IC / 2)];

// prep: x transpose+convert (packed F2FP); weight convert in 9 blocks
__global__ void prep_kernel(const float* __restrict__ x,
                            const float* __restrict__ wg) {
    __shared__ __half s[128 * 66];
    const int h = blockIdx.x, n = blockIdx.y, tid = threadIdx.x;
    const float* src = x + ((size_t)n * IC * HH + h) * WW;
    #pragma unroll
    for (int i = 0; i < 16; i++) {
        int idx = tid + i * 256;
        int icp = idx >> 7;
        int w   = idx & 127;
        float v0 = src[(size_t)(2 * icp)     * (HH * WW) + w];
        float v1 = src[(size_t)(2 * icp + 1) * (HH * WW) + w];
        *(__half2*)&s[w * 66 + 2 * icp] = __floats2half2_rn(v0, v1);
    }
    __syncthreads();
    __half2* dst = g_xh + ((size_t)(n * HH + h)) * (WW * 32);
    #pragma unroll
    for (int i = 0; i < 16; i++) {
        int idx = tid + i * 256;
        int w = idx >> 5, icp = idx & 31;
        dst[w * 32 + icp] = *(__half2*)&s[w * 66 + 2 * icp];
    }
    if (n == 0 && h < 9) {
        const int kk = h;
        #pragma unroll
        for (int i = 0; i < 16; i++) {
            int idx = tid + i * 256;
            int oc  = idx >> 5;
            int ic  = (idx & 31) * 2;
            g_wh[kk * (OCH * 32) + idx] =
                __floats2half2_rn(wg[(oc * IC + ic) * 9 + kk],
                                  wg[(oc * IC + ic + 1) * 9 + kk]);
        }
    }
}

__device__ __forceinline__ uint32_t smem_u32(const void* p) {
    uint32_t a;
    asm("{ .reg .u64 t; cvta.to.shared.u64 t, %1; cvt.u32.u64 %0, t; }"
        : "=r"(a) : "l"(p));
    return a;
}
__device__ __forceinline__ void cp16(uint32_t dst, const void* src) {
    asm volatile("cp.async.cg.shared.global [%0], [%1], 16;"
                 :: "r"(dst), "l"(src));
}
__device__ __forceinline__ void ldsm_x4(uint32_t& r0, uint32_t& r1,
                                        uint32_t& r2, uint32_t& r3,
                                        uint32_t addr) {
    asm volatile("ldmatrix.sync.aligned.m8n8.x4.shared.b16 {%0,%1,%2,%3}, [%4];"
                 : "=r"(r0), "=r"(r1), "=r"(r2), "=r"(r3) : "r"(addr));
}
__device__ __forceinline__ void hmma16816(float* c, const uint32_t* a,
                                          uint32_t b0, uint32_t b1) {
    asm volatile(
        "mma.sync.aligned.m16n8k16.row.col.f32.f16.f16.f32 "
        "{%0,%1,%2,%3}, {%4,%5,%6,%7}, {%8,%9}, {%0,%1,%2,%3};"
        : "+f"(c[0]), "+f"(c[1]), "+f"(c[2]), "+f"(c[3])
        : "r"(a[0]), "r"(a[1]), "r"(a[2]), "r"(a[3]), "r"(b0), "r"(b1));
}
__device__ __forceinline__ float frcp(float v) {
    float r;
    asm("rcp.approx.f32 %0, %1;" : "=f"(r) : "f"(v));
    return r;
}

__global__ void __launch_bounds__(512, 1)
conv_hmma_kernel(const float* __restrict__ bias,
                 float* __restrict__ out)
{
    extern __shared__ char smem[];
    const uint32_t sbase = smem_u32(smem);

    const int tid  = threadIdx.x;
    const int lane = tid & 31;
    const int warp = tid >> 5;       // 0..15
    const int g    = lane >> 2;
    const int t    = lane & 3;

    const int warp_m = warp & 3;     // 4 warps over M=256 (64 each)
    const int warp_n = warp >> 2;    // 4 warps over N=128 (32 each)
    const int wmh = warp_m >> 1;     // which oh row of the pair
    const int wml = warp_m & 1;      // which 64-wide m half

    // ---- contiguous tile range for this CTA
    const int P = gridDim.x;
    const int base = TILES / P;
    const int rem  = TILES - base * P;
    const int p    = blockIdx.x;
    const int start = p * base + (p < rem ? p : rem);
    const int len   = base + (p < rem ? 1 : 0);
    if (len == 0) return;
    int n   = start / OHP;
    int ohp = start - n * OHP;

    // ---- per-lane ldmatrix constants
    const int l7  = lane & 7;
    const int m8  = (lane >> 3) & 1;
    const int k01w = (lane >> 4) & 1;           // A: k 16B half
    // A (padded 144B rows, [w][ic]):
    const uint32_t a_lane =
        (uint32_t)(((l7 + m8 * 8) * XSTR + k01w * 8) * 2);
    // B (swizzled 128B rows, [oc][ic]): row=oc, chunk cb = ks*2 + k01
    const int k01b = (lane >> 3) & 1;
    const int oc8  = (lane >> 4) & 1;
    const uint32_t bConst = WOFF +
        (uint32_t)((warp_n * 32 + l7 + oc8 * 8) * 128) +
        (uint32_t)((k01b ^ (l7 & 1)) * 16);
    uint32_t offk[4];
    #pragma unroll
    for (int ks = 0; ks < 4; ks++)
        offk[ks] = (uint32_t)(((ks * 2) ^ (l7 & 6)) * 16);

    // ---- staging helpers (512 threads)
    auto stage_row = [&](int nn, int ih) {      // 1024 cp16
        const __half* xr = (const __half*)g_xh +
                           ((size_t)(nn * HH + ih)) * (WW * IC);
        const uint32_t slotb = (uint32_t)((ih & 3) * SX_BYTES);
        #pragma unroll
        for (int i = 0; i < 2; i++) {
            int idx = tid + i * 512;
            int w = idx >> 3, cc = idx & 7;
            cp16(sbase + slotb + (uint32_t)((w * XSTR + cc * 8) * 2),
                 xr + w * IC + cc * 8);
        }
    };

    // ---- prologue: all 9 taps (swizzled) + 4 x rows, once per CTA
    {
        const __half* wr = (const __half*)g_wh;
        #pragma unroll
        for (int i = 0; i < 18; i++) {
            int idx = tid + i * 512;             // 0..9215
            int kk  = idx >> 10;
            int r   = idx & 1023;
            int oc  = r >> 3, cc = r & 7;
            cp16(sbase + WOFF + (uint32_t)(kk * WTAP + oc * 128 +
                     ((cc ^ (oc & 7)) << 4)),
                 wr + (kk * OCH + oc) * IC + cc * 8);
        }
        const int oh0p = 2 * ohp;
        for (int r = 0; r < 4; r++) stage_row(n, oh0p + r);
        asm volatile("cp.async.commit_group;" ::: "memory");
        asm volatile("cp.async.wait_group 0;" ::: "memory");
        __syncthreads();
    }

    // ---- tap body
    float c[4][4][4];
    auto tap = [&](int kk, int oh03) {
        const int kh = kk / 3, kw = kk % 3;
        const int slot = (oh03 + kh + wmh) & 3;
        const uint32_t aB = sbase + (uint32_t)(slot * SX_BYTES) + a_lane +
                            (uint32_t)((wml * 64 + kw) * 144);
        const uint32_t bB = sbase + bConst + (uint32_t)(kk * WTAP);
        #pragma unroll
        for (int ks = 0; ks < 4; ks++) {
            uint32_t a[4][4];
            #pragma unroll
            for (int i = 0; i < 4; i++)
                ldsm_x4(a[i][0], a[i][1], a[i][2], a[i][3],
                        aB + (uint32_t)(i * 2304 + ks * 32));
            #pragma unroll
            for (int jp = 0; jp < 2; jp++) {
                uint32_t b0, b1, b2, b3;
                ldsm_x4(b0, b1, b2, b3, bB + (uint32_t)(jp * 2048) + offk[ks]);
                #pragma unroll
                for (int i = 0; i < 4; i++) {
                    hmma16816(c[i][jp * 2],     a[i], b0, b1);
                    hmma16816(c[i][jp * 2 + 1], a[i], b2, b3);
                }
            }
        }
    };

    // ---- persistent tile loop
    for (int ti = 0; ti < len; ti++) {
        const int oh0  = 2 * ohp;
        const int oh03 = oh0 & 3;

        #pragma unroll
        for (int i = 0; i < 4; i++)
            #pragma unroll
            for (int j = 0; j < 4; j++)
                #pragma unroll
                for (int r = 0; r < 4; r++)
                    c[i][j][r] = 0.f;

        // kh = 0, 1 taps (read x rows oh0 .. oh0+2)
        #pragma unroll
        for (int kk = 0; kk < 6; kk++) tap(kk, oh03);

        __syncthreads();   // all reads of rows oh0, oh0+1 complete

        const bool more = (ti + 1 < len);
        const bool cont = more && (ohp + 1 < OHP);
        if (cont) {        // next tile same n: rows oh0+4, oh0+5 into freed slots
            stage_row(n, oh0 + 4);
            stage_row(n, oh0 + 5);
            asm volatile("cp.async.commit_group;" ::: "memory");
        }

        // kh = 2 taps (read x rows oh0+2, oh0+3)
        #pragma unroll
        for (int kk = 6; kk < 9; kk++) tap(kk, oh03);

        // ---- epilogue: bias, -0.7, Mish (paired rcp)
        {
            const int oh = oh0 + wmh;
            #pragma unroll
            for (int j = 0; j < 4; j++) {
                const int oc0 = warp_n * 32 + j * 8 + 2 * t;
                const float b0 = bias[oc0]     - 0.7f;
                const float b1 = bias[oc0 + 1] - 0.7f;
                #pragma unroll
                for (int i = 0; i < 4; i++) {
                    #pragma unroll
                    for (int pp = 0; pp < 4; pp += 2) {
                        const int m = wml * 64 + i * 16 + g + ((pp & 2) ? 8 : 0);
                        if (m >= OW) continue;
                        float v0 = c[i][j][pp]     + b0;
                        float v1 = c[i][j][pp + 1] + b1;
                        float e0 = __expf(fminf(v0, 15.f));
                        float e1 = __expf(fminf(v1, 15.f));
                        float n0 = e0 * (e0 + 2.f);
                        float n1 = e1 * (e1 + 2.f);
                        float d0 = n0 + 2.f, d1 = n1 + 2.f;
                        float rr = frcp(d0 * d1);
                        float m0 = v0 * n0 * (rr * d1);
                        float m1 = v1 * n1 * (rr * d0);
                        float* ob = out +
                            ((size_t)(n * OCH + oc0) * OH + oh) * OW + m;
                        ob[0]                 = m0;
                        ob[(size_t)(OH * OW)] = m1;
                    }
                }
            }
        }

        if (more && !cont) {   // n boundary: restage all 4 rows for next tile
            __syncthreads();   // kh=2 reads of rows oh0+2, oh0+3 complete
            for (int r = 0; r < 4; r++) stage_row(n + 1, r);
            asm volatile("cp.async.commit_group;" ::: "memory");
        }

        ohp++;
        if (ohp == OHP) { ohp = 0; n++; }
        if (more) {
            asm volatile("cp.async.wait_group 0;" ::: "memory");
            __syncthreads();
        }
    }
}

extern "C" void kernel_launch(void* const* d_in, const int* in_sizes, int n_in,
                              void* d_out, int out_size) {
    const float* x  = (const float*)d_in[0];
    const float* w  = (const float*)d_in[1];
    const float* b  = (const float*)d_in[2];
    float* out      = (float*)d_out;

    {
        dim3 tg(HH, NB);
        prep_kernel<<<tg, 256>>>(x, w);
    }

    int nsm = 148;
    cudaDeviceGetAttribute(&nsm, cudaDevAttrMultiProcessorCount, 0);
    int grid = nsm < TILES ? nsm : TILES;

    cudaFuncSetAttribute(conv_hmma_kernel,
                         cudaFuncAttributeMaxDynamicSharedMemorySize, SMEM_BYTES);
    conv_hmma_kernel<<<grid, 512, SMEM_BYTES>>>(b, out);
}